// round 14
// baseline (speedup 1.0000x reference)
#include <cuda_runtime.h>
#include <cstdint>

#define N_PULSES 64
#define N_STATES 21

__global__ __launch_bounds__(256)
void epg_kernel(const float* __restrict__ flip,
                const float* __restrict__ phases,
                const float* __restrict__ T1,
                const float* __restrict__ T2,
                const float* __restrict__ B0,
                const float* __restrict__ B1,
                const void*  __restrict__ trp,
                float* __restrict__ out,
                int B)
{
    // Per-pulse trig, computed once per block (5 scalar arrays — R7 structure)
    __shared__ float s_cb[N_PULSES], s_sb[N_PULSES], s_c2b[N_PULSES], s_s2b[N_PULSES], s_a[N_PULSES];

    int tid = threadIdx.x;
    if (tid < N_PULSES) {
        float bph = phases[tid];
        float sb, cb;
        sincosf(bph, &sb, &cb);
        s_cb[tid]  = cb;
        s_sb[tid]  = sb;
        s_c2b[tid] = cb * cb - sb * sb;
        s_s2b[tid] = 2.0f * cb * sb;
        s_a[tid]   = flip[tid];          // full flip angle (identity form)
    }
    __syncthreads();

    int gwarp = (int)((blockIdx.x * blockDim.x + tid) >> 5);
    int lane  = tid & 31;

    // Two independent batch elements per warp
    int b0 = 2 * gwarp;
    int b1 = b0 + 1;
    if (b0 >= B) return;
    bool has1 = (b1 < B);
    int b1c = has1 ? b1 : b0;

    // TR: defensive decode (int32 / float32 both yield 500)
    float TRf;
    {
        int iv = *(const int*)trp;
        if (iv > 0 && iv < 1000000) TRf = (float)iv;
        else                        TRf = *(const float*)trp;
    }

    float E1a = expf(-TRf / T1[b0]);
    float E1b = expf(-TRf / T1[b1c]);
    float E2a = expf(-TRf / T2[b0]);
    float E2b = expf(-TRf / T2[b1c]);
    float recA = (lane == 0) ? (1.0f - E1a) : 0.0f;
    float recB = (lane == 0) ? (1.0f - E1b) : 0.0f;
    float b1va = B1[b0];
    float b1vb = B1[b1c];

    const float TWO_PI_OVER_1000 = 6.283185307179586e-3f;
    float sphA, cphA, sphB, cphB;
    sincosf(TWO_PI_OVER_1000 * B0[b0]  * TRf, &sphA, &cphA);
    sincosf(TWO_PI_OVER_1000 * B0[b1c] * TRf, &sphB, &cphB);

    float cEa = E2a * cphA, sEa = E2a * sphA;
    float cEb = E2b * cphB, sEb = E2b * sphB;

    // Two independent state sets
    float FpRa = 0.f, FpIa = 0.f, FmRa = 0.f, FmIa = 0.f;
    float FpRb = 0.f, FpIb = 0.f, FmRb = 0.f, FmIb = 0.f;
    float Za = (lane == 0) ? 1.0f : 0.0f;
    float Zb = Za;

    size_t planeStride = (size_t)B * N_STATES;       // RUNTIME stride (schedule-critical)
    float* outp = out + (size_t)b0 * N_STATES + lane; // element b1 at +N_STATES immediate
    bool st0 = (lane < N_STATES);
    bool st1 = st0 && has1;
    bool isLane0 = (lane == 0);
    bool isLast  = (lane == N_STATES - 1);

    #pragma unroll 2
    for (int p = 0; p < N_PULSES; p++) {
        // ---- fused E2 relaxation + B0 rotation ----
        float r;
        r    = FpRa * cEa - FpIa * sEa;  FpIa = FpRa * sEa + FpIa * cEa;  FpRa = r;
        r    = FmRa * cEa + FmIa * sEa;  FmIa = FmIa * cEa - FmRa * sEa;  FmRa = r;
        r    = FpRb * cEb - FpIb * sEb;  FpIb = FpRb * sEb + FpIb * cEb;  FpRb = r;
        r    = FmRb * cEb + FmIb * sEb;  FmIb = FmIb * cEb - FmRb * sEb;  FmRb = r;

        Za = Za * E1a + recA;
        Zb = Zb * E1b + recB;

        // ---- RF mixing: full-angle hardware sincos ----
        float aP = s_a[p];
        float cb  = s_cb[p],  sb  = s_sb[p];
        float c2b = s_c2b[p], s2b = s_s2b[p];

        float sinA, cosA, sinB, cosB;
        __sincosf(aP * b1va, &sinA, &cosA);
        __sincosf(aP * b1vb, &sinB, &cosB);
        float ca2a = 0.5f + 0.5f * cosA, sa2a = 0.5f - 0.5f * cosA, csA = 0.5f * sinA;
        float ca2b = 0.5f + 0.5f * cosB, sa2b = 0.5f - 0.5f * cosB, csB = 0.5f * sinB;

        float cZa = csA * Za, cZsbA = cZa * sb, cZcbA = cZa * cb;
        float cZb = csB * Zb, cZsbB = cZb * sb, cZcbB = cZb * cb;

        float FpnRa = ca2a * FpRa + sa2a * ( FmRa * c2b + FmIa * s2b) - cZsbA;
        float FpnIa = ca2a * FpIa + sa2a * ( FmRa * s2b - FmIa * c2b) + cZcbA;
        float FmnRa = ca2a * FmRa + sa2a * ( FpRa * c2b - FpIa * s2b) - cZsbA;
        float FmnIa = ca2a * FmIa + sa2a * (-FpRa * s2b - FpIa * c2b) - cZcbA;
        float DimA  = (FpIa * cb - FpRa * sb) - (FmRa * sb + FmIa * cb);
        float ZnA   = csA * DimA + cosA * Za;

        float FpnRb = ca2b * FpRb + sa2b * ( FmRb * c2b + FmIb * s2b) - cZsbB;
        float FpnIb = ca2b * FpIb + sa2b * ( FmRb * s2b - FmIb * c2b) + cZcbB;
        float FmnRb = ca2b * FmRb + sa2b * ( FpRb * c2b - FpIb * s2b) - cZsbB;
        float FmnIb = ca2b * FmIb + sa2b * (-FpRb * s2b - FpIb * c2b) - cZcbB;
        float DimB  = (FpIb * cb - FpRb * sb) - (FmRb * sb + FmIb * cb);
        float ZnB   = csB * DimB + cosB * Zb;

        // ---- gradient shift (8 independent shuffles) ----
        float uRa = __shfl_up_sync  (0xffffffffu, FpnRa, 1);
        float uIa = __shfl_up_sync  (0xffffffffu, FpnIa, 1);
        float dRa = __shfl_down_sync(0xffffffffu, FmnRa, 1);
        float dIa = __shfl_down_sync(0xffffffffu, FmnIa, 1);
        float uRb = __shfl_up_sync  (0xffffffffu, FpnRb, 1);
        float uIb = __shfl_up_sync  (0xffffffffu, FpnIb, 1);
        float dRb = __shfl_down_sync(0xffffffffu, FmnRb, 1);
        float dIb = __shfl_down_sync(0xffffffffu, FmnIb, 1);
        if (isLane0) { uRa = 0.f; uIa = 0.f; uRb = 0.f; uIb = 0.f; }
        if (isLast)  { dRa = 0.f; dIa = 0.f; dRb = 0.f; dIb = 0.f; }
        FpRa = uRa; FpIa = uIa; FmRa = dRa; FmIa = dIa; Za = ZnA;
        FpRb = uRb; FpIb = uIb; FmRb = dRb; FmIb = dIb; Zb = ZnB;

        // ---- stores: per-iteration independent base; elem b1 via +N_STATES immediates ----
        float* o = outp + (size_t)(p * 5) * planeStride;
        if (st0) {
            o[0]                           = FpRa;
            o[planeStride]                 = FpIa;
            o[2 * planeStride]             = FmRa;
            o[3 * planeStride]             = FmIa;
            o[4 * planeStride]             = ZnA;
        }
        if (st1) {
            o[N_STATES]                    = FpRb;
            o[planeStride + N_STATES]      = FpIb;
            o[2 * planeStride + N_STATES]  = FmRb;
            o[3 * planeStride + N_STATES]  = FmIb;
            o[4 * planeStride + N_STATES]  = ZnB;
        }
    }
}

extern "C" void kernel_launch(void* const* d_in, const int* in_sizes, int n_in,
                              void* d_out, int out_size)
{
    const float* flip   = (const float*)d_in[0];
    const float* phases = (const float*)d_in[1];
    const float* T1     = (const float*)d_in[2];
    const float* T2     = (const float*)d_in[3];
    const float* B0     = (const float*)d_in[4];
    const float* B1     = (const float*)d_in[5];
    const void*  trp    = d_in[6];
    float* out = (float*)d_out;

    int B = in_sizes[2];               // batch from T1
    int threads = 256;
    int warpsPerBlock = threads / 32;  // 8
    int elemsPerBlock = warpsPerBlock * 2;
    int blocks = (B + elemsPerBlock - 1) / elemsPerBlock;

    epg_kernel<<<blocks, threads>>>(flip, phases, T1, T2, B0, B1, trp, out, B);
}

// round 15
// speedup vs baseline: 1.0998x; 1.0998x over previous
#include <cuda_runtime.h>
#include <cstdint>

#define N_PULSES 64
#define N_STATES 21

__global__ __launch_bounds__(256)
void epg_kernel(const float* __restrict__ flip,
                const float* __restrict__ phases,
                const float* __restrict__ T1,
                const float* __restrict__ T2,
                const float* __restrict__ B0,
                const float* __restrict__ B1,
                const void*  __restrict__ trp,
                float* __restrict__ out,
                int B)
{
    // Per-pulse trig, computed once per block (5 scalar arrays — schedule-critical form)
    __shared__ float s_cb[N_PULSES], s_sb[N_PULSES], s_c2b[N_PULSES], s_s2b[N_PULSES], s_ha[N_PULSES];

    int tid = threadIdx.x;
    if (tid < N_PULSES) {
        float bph = phases[tid];
        float sb, cb;
        sincosf(bph, &sb, &cb);
        s_cb[tid]  = cb;
        s_sb[tid]  = sb;
        s_c2b[tid] = cb * cb - sb * sb;
        s_s2b[tid] = 2.0f * cb * sb;
        s_ha[tid]  = 0.5f * flip[tid];
    }
    __syncthreads();

    int gwarp = (int)((blockIdx.x * blockDim.x + tid) >> 5);
    int lane  = tid & 31;
    if (gwarp >= B) return;
    int b = gwarp;

    // TR: defensive decode (int32 / float32 both yield 500)
    float TRf;
    {
        int iv = *(const int*)trp;
        if (iv > 0 && iv < 1000000) TRf = (float)iv;
        else                        TRf = *(const float*)trp;
    }

    float t1v = T1[b], t2v = T2[b], b0v = B0[b], b1v = B1[b];
    float E1 = expf(-TRf / t1v);
    float E2 = expf(-TRf / t2v);
    float recov = (lane == 0) ? (1.0f - E1) : 0.0f;   // unpredicated FFMA operand

    // Accurate prologue trig: |phi| can reach ~500 rad; __sincosf error there
    // (~2e-4 abs) would amplify x64 through the recurrence and blow the budget.
    float phi = 2.0f * 3.14159265358979f * b0v * TRf * 0.001f;
    float sphi, cphi;
    sincosf(phi, &sphi, &cphi);

    // Fused relaxation + off-resonance: Fp *= E2*e^{+i phi}, Fm *= E2*e^{-i phi}
    float cE = E2 * cphi;
    float sE = E2 * sphi;

    // State (per lane = per EPG order). Lanes >= N_STATES carry junk but stay in lockstep.
    float FpR = 0.f, FpI = 0.f, FmR = 0.f, FmI = 0.f;
    float Z = (lane == 0) ? 1.0f : 0.0f;

    size_t planeStride = (size_t)B * N_STATES;       // RUNTIME stride (schedule-critical)
    float* outp = out + (size_t)b * N_STATES + lane;

    #pragma unroll 4
    for (int p = 0; p < N_PULSES; p++) {
        // Fused E2 relaxation + B0 rotation (one complex multiply each)
        float r;
        r   = FpR * cE - FpI * sE;
        FpI = FpR * sE + FpI * cE;
        FpR = r;
        r   = FmR * cE + FmI * sE;
        FmI = FmI * cE - FmR * sE;
        FmR = r;

        // Z relaxation + recovery in one FFMA (recov is 0 except lane 0)
        Z = Z * E1 + recov;

        // RF pulse mixing — hardware sincos on alpha/2 (small argument, accurate)
        float sa, ca;
        __sincosf(s_ha[p] * b1v, &sa, &ca);
        float cb  = s_cb[p],  sb  = s_sb[p];
        float c2b = s_c2b[p], s2b = s_s2b[p];
        float ca2 = ca * ca, sa2 = sa * sa, casa = ca * sa;
        float cZ   = casa * Z;
        float cZsb = cZ * sb;
        float cZcb = cZ * cb;

        float FpnR = ca2 * FpR + sa2 * ( FmR * c2b + FmI * s2b) - cZsb;
        float FpnI = ca2 * FpI + sa2 * ( FmR * s2b - FmI * c2b) + cZcb;
        float FmnR = ca2 * FmR + sa2 * ( FpR * c2b - FpI * s2b) - cZsb;
        float FmnI = ca2 * FmI + sa2 * (-FpR * s2b - FpI * c2b) - cZcb;
        float Dim  = (FpI * cb - FpR * sb) - (FmR * sb + FmI * cb);
        float Zn   = casa * Dim + (ca2 - sa2) * Z;

        // Gradient shift: Fp states move up one order, Fm down one order
        float FpsR = __shfl_up_sync(0xffffffffu, FpnR, 1);
        float FpsI = __shfl_up_sync(0xffffffffu, FpnI, 1);
        float FmsR = __shfl_down_sync(0xffffffffu, FmnR, 1);
        float FmsI = __shfl_down_sync(0xffffffffu, FmnI, 1);
        if (lane == 0)            { FpsR = 0.f; FpsI = 0.f; }
        if (lane == N_STATES - 1) { FmsR = 0.f; FmsI = 0.f; }
        FpR = FpsR; FpI = FpsI; FmR = FmsR; FmI = FmsI; Z = Zn;

        // Store outs[p, 0..4, b, lane] — per-iteration independent runtime addresses
        // (this addressing form induces ptxas's 80-reg high-issue schedule; do not
        // replace with incremental pointers or compile-time strides)
        if (lane < N_STATES) {
            float* o = outp + (size_t)(p * 5) * planeStride;
            o[0]               = FpR;
            o[planeStride]     = FpI;
            o[2 * planeStride] = FmR;
            o[3 * planeStride] = FmI;
            o[4 * planeStride] = Zn;
        }
    }
}

extern "C" void kernel_launch(void* const* d_in, const int* in_sizes, int n_in,
                              void* d_out, int out_size)
{
    const float* flip   = (const float*)d_in[0];
    const float* phases = (const float*)d_in[1];
    const float* T1     = (const float*)d_in[2];
    const float* T2     = (const float*)d_in[3];
    const float* B0     = (const float*)d_in[4];
    const float* B1     = (const float*)d_in[5];
    const void*  trp    = d_in[6];
    float* out = (float*)d_out;

    int B = in_sizes[2];               // batch from T1
    int threads = 256;
    int warpsPerBlock = threads / 32;
    int blocks = (B + warpsPerBlock - 1) / warpsPerBlock;

    epg_kernel<<<blocks, threads>>>(flip, phases, T1, T2, B0, B1, trp, out, B);
}